// round 11
// baseline (speedup 1.0000x reference)
#include <cuda_runtime.h>
#include <cuda_bf16.h>
#include <cstdint>

#define BB 8
#define SS 1024
#define DD 1024
#define HH 8
#define DH 128
#define NN 3072
#define SCALE 0.08838834764831845f   // 1/sqrt(128)

// ---------------------------------------------------------------------------
// Device scratch
// ---------------------------------------------------------------------------
__device__ __nv_bfloat16 g_kh[BB*HH*SS*DH];   // K hi  [bh][s][d]
__device__ __nv_bfloat16 g_kl[BB*HH*SS*DH];   // K lo
__device__ __nv_bfloat16 g_qh[BB*HH*SS*DH];   // Q hi  [bh][s][d]
__device__ __nv_bfloat16 g_ql[BB*HH*SS*DH];   // Q lo
__device__ __nv_bfloat16 g_vth[BB*HH*DH*SS];  // V^T hi [bh][d][s]
__device__ float g_inv[BB*HH*SS];             // 1/rowsum
__device__ __nv_bfloat16 g_Ah[BB*SS*DD];
__device__ __nv_bfloat16 g_Al[BB*SS*DD];
__device__ __nv_bfloat16 g_Wh[NN*DD];
__device__ __nv_bfloat16 g_Wl[NN*DD];

// ---------------------------------------------------------------------------
// Split conversion
// ---------------------------------------------------------------------------
__device__ __forceinline__ void split4(float4 v, __nv_bfloat162* hi2, __nv_bfloat162* lo2) {
    __nv_bfloat16 hx = __float2bfloat16_rn(v.x);
    __nv_bfloat16 hy = __float2bfloat16_rn(v.y);
    __nv_bfloat16 hz = __float2bfloat16_rn(v.z);
    __nv_bfloat16 hw = __float2bfloat16_rn(v.w);
    hi2[0] = __nv_bfloat162(hx, hy);
    hi2[1] = __nv_bfloat162(hz, hw);
    lo2[0] = __nv_bfloat162(__float2bfloat16_rn(v.x - __bfloat162float(hx)),
                            __float2bfloat16_rn(v.y - __bfloat162float(hy)));
    lo2[1] = __nv_bfloat162(__float2bfloat16_rn(v.z - __bfloat162float(hz)),
                            __float2bfloat16_rn(v.w - __bfloat162float(hw)));
}

__global__ __launch_bounds__(256) void convA_kernel(const float* __restrict__ A) {
    int i4 = blockIdx.x * 256 + threadIdx.x;
    if (i4 >= BB*SS*DD/4) return;
    float4 v = ((const float4*)A)[i4];
    __nv_bfloat162 h[2], l[2];
    split4(v, h, l);
    ((__nv_bfloat162*)g_Ah)[i4*2]   = h[0];
    ((__nv_bfloat162*)g_Ah)[i4*2+1] = h[1];
    ((__nv_bfloat162*)g_Al)[i4*2]   = l[0];
    ((__nv_bfloat162*)g_Al)[i4*2+1] = l[1];
}

__global__ __launch_bounds__(256) void convW_kernel(const float* __restrict__ c_w,
                                                    const float* __restrict__ v_w) {
    int i4 = blockIdx.x * 256 + threadIdx.x;
    if (i4 >= NN*DD/4) return;
    int e = i4 * 4;
    int n = e >> 10, k = e & 1023;
    const float* src = (n < DD) ? (v_w + (size_t)n * DD + k)
                                : (c_w + (size_t)(n - DD) * DD + k);
    float4 v = *(const float4*)src;
    __nv_bfloat162 h[2], l[2];
    split4(v, h, l);
    ((__nv_bfloat162*)g_Wh)[i4*2]   = h[0];
    ((__nv_bfloat162*)g_Wh)[i4*2+1] = h[1];
    ((__nv_bfloat162*)g_Wl)[i4*2]   = l[0];
    ((__nv_bfloat162*)g_Wl)[i4*2+1] = l[1];
}

// ---------------------------------------------------------------------------
// helpers
// ---------------------------------------------------------------------------
__device__ __forceinline__ uint32_t smem_u32(const void* p) {
    uint32_t a;
    asm("{ .reg .u64 t; cvta.to.shared.u64 t, %1; cvt.u32.u64 %0, t; }" : "=r"(a) : "l"(p));
    return a;
}
__device__ __forceinline__ void ldsm_x4(uint32_t* r, uint32_t addr) {
    asm volatile("ldmatrix.sync.aligned.m8n8.x4.shared.b16 {%0,%1,%2,%3}, [%4];"
                 : "=r"(r[0]), "=r"(r[1]), "=r"(r[2]), "=r"(r[3]) : "r"(addr));
}
__device__ __forceinline__ void mma_bf16(float* c, const uint32_t* a, uint32_t b0, uint32_t b1) {
    asm volatile(
        "mma.sync.aligned.m16n8k16.row.col.f32.bf16.bf16.f32 "
        "{%0,%1,%2,%3}, {%4,%5,%6,%7}, {%8,%9}, {%0,%1,%2,%3};"
        : "+f"(c[0]), "+f"(c[1]), "+f"(c[2]), "+f"(c[3])
        : "r"(a[0]), "r"(a[1]), "r"(a[2]), "r"(a[3]), "r"(b0), "r"(b1));
}
__device__ __forceinline__ void cpa16ca(uint32_t dst, const void* src) {
    asm volatile("cp.async.ca.shared.global [%0], [%1], 16;" :: "r"(dst), "l"(src));
}
__device__ __forceinline__ void cpa16cg(uint32_t dst, const void* src) {
    asm volatile("cp.async.cg.shared.global [%0], [%1], 16;" :: "r"(dst), "l"(src));
}
#define CP_COMMIT() asm volatile("cp.async.commit_group;")
#define CP_WAIT(n)  asm volatile("cp.async.wait_group %0;" :: "n"(n))

__device__ __forceinline__ void store_hilo(__nv_bfloat16* bh_, __nv_bfloat16* bl_,
                                           size_t off, float x0, float x1) {
    __nv_bfloat16 h0 = __float2bfloat16_rn(x0), h1 = __float2bfloat16_rn(x1);
    *(__nv_bfloat162*)(bh_ + off) = __nv_bfloat162(h0, h1);
    *(__nv_bfloat162*)(bl_ + off) =
        __nv_bfloat162(__float2bfloat16_rn(x0 - __bfloat162float(h0)),
                       __float2bfloat16_rn(x1 - __bfloat162float(h1)));
}

// ---------------------------------------------------------------------------
// Projection GEMM (split-bf16 HMMA): K/Q 3 passes, V 1 pass. occ 2.
// ---------------------------------------------------------------------------
#define KC 32
#define ROWP 40
#define BUF_E (128*ROWP)
#define OFF_AH 0
#define OFF_AL (2*BUF_E)
#define OFF_BH (4*BUF_E)
#define OFF_BL (6*BUF_E)
#define GEMM_SMEM_B (8*BUF_E*2 + 512)

__device__ __forceinline__ void issue_op(uint32_t sdst, const __nv_bfloat16* g,
                                         int tid, int k0) {
#pragma unroll
    for (int j = 0; j < 2; j++) {
        int u = tid + j * 256;
        int row = u >> 2, seg = u & 3;
        cpa16ca(sdst + (uint32_t)(row * ROWP + seg * 8) * 2,
                g + (size_t)row * DD + k0 + seg * 8);
    }
}

__global__ __launch_bounds__(256, 2) void gemm_kernel(const float* __restrict__ c_b,
                                                      const float* __restrict__ v_b) {
    extern __shared__ __nv_bfloat16 sm[];
    float* sBias = (float*)(sm + 8 * BUF_E);
    const uint32_t sbase = smem_u32(sm);

    const int tid  = threadIdx.x;
    const int lane = tid & 31;
    const int wid  = tid >> 5;
    const int wm   = wid >> 1;
    const int wn   = wid & 1;
    const int n0   = blockIdx.x * 128;
    const int m0   = blockIdx.y * 128;
    const int kind = n0 >> 10;
    const bool vpath = (kind == 2);

    const __nv_bfloat16* Ah = g_Ah + (size_t)m0 * DD;
    const __nv_bfloat16* Al = g_Al + (size_t)m0 * DD;
    const __nv_bfloat16* Bh = g_Wh + (size_t)n0 * DD;
    const __nv_bfloat16* Bl = g_Wl + (size_t)n0 * DD;

    const float* bp = (n0 < DD) ? (v_b + n0) : (c_b + (n0 - DD));
    if (tid < 128) sBias[tid] = bp[tid];

    float acc[2][8][4];
#pragma unroll
    for (int i = 0; i < 2; i++)
#pragma unroll
        for (int j = 0; j < 8; j++)
#pragma unroll
            for (int c = 0; c < 4; c++) acc[i][j][c] = 0.f;

    const int lrow_a = wm * 32 + (lane & 15);
    const int lrow_b0 = wn * 64 + (lane & 15);
    const int lk = ((lane >> 4) & 1) * 8;

    {
        issue_op(sbase + OFF_AH * 2, Ah, tid, 0);
        issue_op(sbase + OFF_BH * 2, Bh, tid, 0);
        if (!vpath) {
            issue_op(sbase + OFF_AL * 2, Al, tid, 0);
            issue_op(sbase + OFF_BL * 2, Bl, tid, 0);
        }
        CP_COMMIT();
    }

#pragma unroll 1
    for (int c = 0; c < DD / KC; c++) {
        const int cur = c & 1;
        if (c + 1 < DD / KC) {
            uint32_t bu = sbase + (uint32_t)((cur ^ 1) * BUF_E) * 2;
            int k0 = (c + 1) * KC;
            issue_op(bu + OFF_AH * 2, Ah, tid, k0);
            issue_op(bu + OFF_BH * 2, Bh, tid, k0);
            if (!vpath) {
                issue_op(bu + OFF_AL * 2, Al, tid, k0);
                issue_op(bu + OFF_BL * 2, Bl, tid, k0);
            }
            CP_COMMIT();
            CP_WAIT(1);
        } else {
            CP_WAIT(0);
        }
        __syncthreads();

        const __nv_bfloat16* base = sm + cur * BUF_E;
#pragma unroll
        for (int kk = 0; kk < 2; kk++) {
            const int ke = kk * 16 + lk;
            uint32_t ah[2][4], al[2][4], bh[4][4], bl[4][4];
#pragma unroll
            for (int mi = 0; mi < 2; mi++) {
                uint32_t ad = smem_u32(base + OFF_AH + (lrow_a + mi * 16) * ROWP + ke);
                ldsm_x4(ah[mi], ad);
                if (!vpath) ldsm_x4(al[mi], ad + (OFF_AL - OFF_AH) * 2);
            }
#pragma unroll
            for (int nb = 0; nb < 4; nb++) {
                uint32_t bd = smem_u32(base + OFF_BH + (lrow_b0 + nb * 16) * ROWP + ke);
                ldsm_x4(bh[nb], bd);
                if (!vpath) ldsm_x4(bl[nb], bd + (OFF_BL - OFF_BH) * 2);
            }
            if (vpath) {
#pragma unroll
                for (int mi = 0; mi < 2; mi++)
#pragma unroll
                    for (int nb = 0; nb < 4; nb++) {
                        mma_bf16(acc[mi][nb*2+0], ah[mi], bh[nb][0], bh[nb][2]);
                        mma_bf16(acc[mi][nb*2+1], ah[mi], bh[nb][1], bh[nb][3]);
                    }
            } else {
#pragma unroll
                for (int mi = 0; mi < 2; mi++)
#pragma unroll
                    for (int nb = 0; nb < 4; nb++) {
                        mma_bf16(acc[mi][nb*2+0], ah[mi], bh[nb][0], bh[nb][2]);
                        mma_bf16(acc[mi][nb*2+1], ah[mi], bh[nb][1], bh[nb][3]);
                        mma_bf16(acc[mi][nb*2+0], ah[mi], bl[nb][0], bl[nb][2]);
                        mma_bf16(acc[mi][nb*2+1], ah[mi], bl[nb][1], bl[nb][3]);
                        mma_bf16(acc[mi][nb*2+0], al[mi], bh[nb][0], bh[nb][2]);
                        mma_bf16(acc[mi][nb*2+1], al[mi], bh[nb][1], bh[nb][3]);
                    }
            }
        }
        __syncthreads();
    }

    const int h = (n0 >> 7) & 7;
    const int b_ = m0 >> 10;
    const int g = lane >> 2;
    const int tc = (lane & 3) * 2;
    const size_t bh_off = (size_t)(b_ * HH + h);

#pragma unroll
    for (int mi = 0; mi < 2; mi++) {
#pragma unroll
        for (int nj = 0; nj < 8; nj++) {
            const float* a4 = acc[mi][nj];
            int d = wn * 64 + nj * 8 + tc;
            float bx = sBias[d], by = sBias[d + 1];
            int s0 = (m0 + wm * 32 + mi * 16 + g) & 1023;
            float x0 = a4[0] + bx, x1 = a4[1] + by;
            float x2 = a4[2] + bx, x3 = a4[3] + by;
            if (kind == 2) {
                __nv_bfloat16* dst = g_vth + bh_off * DH * SS;
                dst[(size_t)d * SS + s0]           = __float2bfloat16_rn(x0);
                dst[(size_t)(d + 1) * SS + s0]     = __float2bfloat16_rn(x1);
                dst[(size_t)d * SS + s0 + 8]       = __float2bfloat16_rn(x2);
                dst[(size_t)(d + 1) * SS + s0 + 8] = __float2bfloat16_rn(x3);
            } else {
                __nv_bfloat16* dh_ = (kind == 0) ? g_kh : g_qh;
                __nv_bfloat16* dl_ = (kind == 0) ? g_kl : g_ql;
                size_t base_off = (bh_off * SS + s0) * DH + d;
                store_hilo(dh_, dl_, base_off, x0, x1);
                store_hilo(dh_, dl_, base_off + 8 * DH, x2, x3);
            }
        }
    }
}

// ---------------------------------------------------------------------------
// attn_scores: TI=128. e = exp(score*SCALE) -> out (w region), 1/rowsum -> g_inv.
// 8 warps 4m x 2n; warp tile 32x32; Q chunk 64 j-rows; occ 2.
// ---------------------------------------------------------------------------
#define KP 136
#define SOFF_KH   0                     // 128x136x2 = 34816
#define SOFF_KL   34816
#define SOFF_QH   69632                 // 64x136x2 = 17408
#define SOFF_QL   87040
#define SOFF_MASK 104448
#define SOFF_SUM  108544                // 128 floats
#define ATTN_S_SMEM 109056

__global__ __launch_bounds__(256, 2) void attn_scores_kernel(
    const int* __restrict__ mask,
    float* __restrict__ out)
{
    extern __shared__ char smc[];
    int*   sMask = (int*)(smc + SOFF_MASK);
    float* sSum  = (float*)(smc + SOFF_SUM);
    const uint32_t uKh = smem_u32(smc) + SOFF_KH;
    const uint32_t uQh = smem_u32(smc) + SOFF_QH;

    const int tid  = threadIdx.x;
    const int lane = tid & 31;
    const int wid  = tid >> 5;
    const int b  = blockIdx.z;
    const int h  = blockIdx.y;
    const int i0 = blockIdx.x * 128;
    const size_t bh = (size_t)(b * HH + h);
    const size_t wbase = (size_t)BB * SS * DD + (bh * SS + i0) * SS;

    const int wm = wid >> 1;        // 0..3 -> rows wm*32
    const int wn = wid & 1;         // 0..1 -> cols wn*32
    const int lr16 = lane & 15;
    const int lkb = (lane >> 4) * 8;
    const int grow = lane >> 2;
    const int gcol = (lane & 3) * 2;

    if (tid < 128) sSum[tid] = 0.f;
    for (int j = tid; j < SS; j += 256) sMask[j] = mask[b * SS + j];
    // K tile fill (128 rows, hi+lo): 2048 units per matrix
#pragma unroll
    for (int it = 0; it < 8; it++) {
        int p = tid + it * 256;
        int row = p >> 4, seg = p & 15;
        size_t go = (bh * SS + i0 + row) * DH + seg * 8;
        uint32_t so = (uint32_t)(row * KP + seg * 8) * 2;
        cpa16cg(uKh + so, g_kh + go);
        cpa16cg(uKh + (SOFF_KL - SOFF_KH) + so, g_kl + go);
    }
    CP_COMMIT();
    CP_WAIT(0);
    __syncthreads();

    float psum[2][2] = {{0.f, 0.f}, {0.f, 0.f}};
#pragma unroll 1
    for (int ct = 0; ct < 16; ct++) {
        // Q chunk fill (64 rows, hi+lo): 1024 units per matrix
#pragma unroll
        for (int it = 0; it < 4; it++) {
            int p = tid + it * 256;
            int row = p >> 4, seg = p & 15;
            size_t go = (bh * SS + ct * 64 + row) * DH + seg * 8;
            uint32_t so = (uint32_t)(row * KP + seg * 8) * 2;
            cpa16cg(uQh + so, g_qh + go);
            cpa16cg(uQh + (SOFF_QL - SOFF_QH) + so, g_ql + go);
        }
        CP_COMMIT();
        CP_WAIT(0);
        __syncthreads();

        float acc[2][4][4];
#pragma unroll
        for (int i = 0; i < 2; i++)
#pragma unroll
            for (int j = 0; j < 4; j++)
#pragma unroll
                for (int cc = 0; cc < 4; cc++) acc[i][j][cc] = 0.f;

#pragma unroll
        for (int ks = 0; ks < 8; ks++) {
            const int ke = ks * 16 + lkb;
            uint32_t kh[2][4], kl[2][4], qh[2][4], ql[2][4];
#pragma unroll
            for (int mi = 0; mi < 2; mi++) {
                uint32_t ad = uKh + (uint32_t)((wm * 32 + mi * 16 + lr16) * KP + ke) * 2;
                ldsm_x4(kh[mi], ad);
                ldsm_x4(kl[mi], ad + (SOFF_KL - SOFF_KH));
            }
#pragma unroll
            for (int nb = 0; nb < 2; nb++) {
                uint32_t bd = uQh + (uint32_t)((wn * 32 + nb * 16 + lr16) * KP + ke) * 2;
                ldsm_x4(qh[nb], bd);
                ldsm_x4(ql[nb], bd + (SOFF_QL - SOFF_QH));
            }
#pragma unroll
            for (int mi = 0; mi < 2; mi++)
#pragma unroll
                for (int nb = 0; nb < 2; nb++) {
                    mma_bf16(acc[mi][nb*2+0], kh[mi], qh[nb][0], qh[nb][2]);
                    mma_bf16(acc[mi][nb*2+1], kh[mi], qh[nb][1], qh[nb][3]);
                    mma_bf16(acc[mi][nb*2+0], kh[mi], ql[nb][0], ql[nb][2]);
                    mma_bf16(acc[mi][nb*2+1], kh[mi], ql[nb][1], ql[nb][3]);
                    mma_bf16(acc[mi][nb*2+0], kl[mi], qh[nb][0], qh[nb][2]);
                    mma_bf16(acc[mi][nb*2+1], kl[mi], qh[nb][1], qh[nb][3]);
                }
        }

#pragma unroll
        for (int mi = 0; mi < 2; mi++)
#pragma unroll
            for (int nj = 0; nj < 4; nj++) {
                int jg = ct * 64 + wn * 32 + (nj >> 1) * 16 + (nj & 1) * 8 + gcol;
                bool m0 = sMask[jg] != 0, m1 = sMask[jg + 1] != 0;
                int ir = wm * 32 + mi * 16 + grow;
                const float* a4 = acc[mi][nj];
                float2 r0, r1;
                r0.x = m0 ? __expf(a4[0] * SCALE) : 1e-37f;
                r0.y = m1 ? __expf(a4[1] * SCALE) : 1e-37f;
                r1.x = m0 ? __expf(a4[2] * SCALE) : 1e-37f;
                r1.y = m1 ? __expf(a4[3] * SCALE) : 1e-37f;
                psum[mi][0] += r0.x + r0.y;
                psum[mi][1] += r1.x + r1.y;
                *(float2*)&out[wbase + (size_t)ir * SS + jg]       = r0;
                *(float2*)&out[wbase + (size_t)(ir + 8) * SS + jg] = r1;
            }
        __syncthreads();
    }

    // row-sum reduction: combine lanes sharing a row, then cross-warp atomics
#pragma unroll
    for (int mi = 0; mi < 2; mi++)
#pragma unroll
        for (int hf = 0; hf < 2; hf++) {
            psum[mi][hf] += __shfl_xor_sync(~0u, psum[mi][hf], 1);
            psum[mi][hf] += __shfl_xor_sync(~0u, psum[mi][hf], 2);
        }
    if ((lane & 3) == 0) {
#pragma unroll
        for (int mi = 0; mi < 2; mi++) {
            atomicAdd(&sSum[wm * 32 + mi * 16 + grow],     psum[mi][0]);
            atomicAdd(&sSum[wm * 32 + mi * 16 + grow + 8], psum[mi][1]);
        }
    }
    __syncthreads();
    if (tid < 128) g_inv[bh * SS + i0 + tid] = 1.0f / sSum[tid];
}

// ---------------------------------------------------------------------------
// attn_pv: per 128-j chunk — e-tile and V-tile in SEPARATE commit groups;
// normalize overlaps the V load. occ 2.
// ---------------------------------------------------------------------------
#define EPITCH 144                    // floats (conflict-free quad reads)
#define VPITCH 136                    // bf16
#define PPITCH 136                    // bf16
#define SOFFB_E   0                   // 64*144*4  = 36864
#define SOFFB_V   36864               // 128*136*2 = 34816
#define SOFFB_P   71680               // 64*136*2  = 17408
#define SOFFB_INV 89088               // 64 floats
#define ATTN_PV_SMEM 89344

__global__ __launch_bounds__(256, 2) void attn_pv_kernel(
    const float* __restrict__ m_feats,
    float* __restrict__ out)
{
    extern __shared__ char smc[];
    float*         sE   = (float*)(smc + SOFFB_E);
    __nv_bfloat16* sPh  = (__nv_bfloat16*)(smc + SOFFB_P);
    float*         sInv = (float*)(smc + SOFFB_INV);
    const uint32_t uE = smem_u32(smc) + SOFFB_E;
    const uint32_t uV = smem_u32(smc) + SOFFB_V;
    const uint32_t uP = smem_u32(smc) + SOFFB_P;

    const int tid  = threadIdx.x;
    const int lane = tid & 31;
    const int wid  = tid >> 5;
    const int b  = blockIdx.z;
    const int h  = blockIdx.y;
    const int i0 = blockIdx.x * 64;
    const size_t bh = (size_t)(b * HH + h);
    const size_t wbase = (size_t)BB * SS * DD + (bh * SS + i0) * SS;

    const int wm = wid >> 2;
    const int wn = wid & 3;
    const int lr16 = lane & 15;
    const int lkb = (lane >> 4) * 8;
    const int grow = lane >> 2;
    const int gcol = (lane & 3) * 2;

    if (tid < 64) sInv[tid] = g_inv[bh * SS + i0 + tid];
    __syncthreads();

    float racc[2][4][4];
#pragma unroll
    for (int i = 0; i < 2; i++)
#pragma unroll
        for (int j = 0; j < 4; j++)
#pragma unroll
            for (int cc = 0; cc < 4; cc++) racc[i][j][cc] = 0.f;

    const int crow = tid >> 2;          // 0..63
    const int cq   = tid & 3;

#pragma unroll 1
    for (int jc = 0; jc < 8; jc++) {
        // group A: e tile (64 rows x 128 fp32)
#pragma unroll
        for (int it = 0; it < 8; it++) {
            int p = tid + it * 256;
            int row = p >> 5, seg = p & 31;
            cpa16cg(uE + (uint32_t)(row * EPITCH + seg * 4) * 4,
                    out + wbase + (size_t)row * SS + jc * 128 + seg * 4);
        }
        CP_COMMIT();
        // group B: V tile (128 d-rows x 128 j bf16)
#pragma unroll
        for (int it = 0; it < 8; it++) {
            int p = tid + it * 256;
            int row = p >> 4, seg = p & 15;
            cpa16cg(uV + (uint32_t)(row * VPITCH + seg * 8) * 2,
                    g_vth + (bh * DH + row) * SS + jc * 128 + seg * 8);
        }
        CP_COMMIT();

        CP_WAIT(1);                 // e tile ready; V still in flight
        __syncthreads();

        // normalize from SMEM: w -> global, bf16 w -> P tile (overlaps V load)
        {
            float inv = sInv[crow];
            const float* erow = sE + crow * EPITCH;
            float* wrow = out + wbase + (size_t)crow * SS + jc * 128;
#pragma unroll
            for (int k = 0; k < 8; k++) {
                int col = cq * 4 + k * 16;
                float4 e4 = *(const float4*)&erow[col];
                float4 w4;
                w4.x = e4.x * inv; w4.y = e4.y * inv;
                w4.z = e4.z * inv; w4.w = e4.w * inv;
                *(float4*)&wrow[col] = w4;
                union { uint2 u; __nv_bfloat162 b2[2]; } pk;
                pk.b2[0] = __nv_bfloat162(__float2bfloat16_rn(w4.x), __float2bfloat16_rn(w4.y));
                pk.b2[1] = __nv_bfloat162(__float2bfloat16_rn(w4.z), __float2bfloat16_rn(w4.w));
                *(uint2*)&sPh[crow * PPITCH + col] = pk.u;
            }
        }
        CP_WAIT(0);                 // V tile ready
        __syncthreads();

#pragma unroll
        for (int ks = 0; ks < 8; ks++) {
            const int ke = ks * 16 + lkb;
            uint32_t pa[2][4], vh[2][4];
#pragma unroll
            for (int mi = 0; mi < 2; mi++)
                ldsm_x4(pa[mi], uP + (uint32_t)((wm * 32 + mi * 16 + lr16) * PPITCH + ke) * 2);
#pragma unroll
            for (int nb = 0; nb < 2; nb++)
                ldsm_x4(vh[nb], uV + (uint32_t)((wn * 32 + nb * 16 + lr16) * VPITCH + ke) * 2);
#pragma unroll
            for (int mi = 0; mi < 2; mi++)
#pragma unroll
                for (int nb = 0; nb < 2; nb++) {
                    mma_bf16(racc[mi][nb*2+0], pa[mi], vh[nb][0], vh[nb][2]);
                    mma_bf16(racc[mi][nb*2+1], pa[mi], vh[nb][1], vh[nb][3]);
                }
        }
        __syncthreads();
    }

    // epilogue: out = m_feats + R (P normalized)
#pragma unroll
    for (int mi = 0; mi < 2; mi++)
#pragma unroll
        for (int nj = 0; nj < 4; nj++) {
            int d = wn * 32 + (nj >> 1) * 16 + (nj & 1) * 8 + gcol;
            int ir = wm * 32 + mi * 16 + grow;
            const float* a4 = racc[mi][nj];
            size_t o0 = ((size_t)b * SS + i0 + ir) * DD + h * DH + d;
            float2 mf0 = *(const float2*)&m_feats[o0];
            *(float2*)&out[o0] = make_float2(mf0.x + a4[0], mf0.y + a4[1]);
            size_t o1 = o0 + (size_t)8 * DD;
            float2 mf1 = *(const float2*)&m_feats[o1];
            *(float2*)&out[o1] = make_float2(mf1.x + a4[2], mf1.y + a4[3]);
        }
}

// ---------------------------------------------------------------------------
extern "C" void kernel_launch(void* const* d_in, const int* in_sizes, int n_in,
                              void* d_out, int out_size)
{
    const float* m_feats = (const float*)d_in[0];
    const int*   mask    = (const int*)d_in[1];
    const float* c_w     = (const float*)d_in[2];
    const float* c_b     = (const float*)d_in[3];
    const float* v_w     = (const float*)d_in[4];
    const float* v_b     = (const float*)d_in[5];
    float* out = (float*)d_out;

    convA_kernel<<<BB*SS*DD/4/256, 256>>>(m_feats);
    convW_kernel<<<NN*DD/4/256, 256>>>(c_w, v_w);

    cudaFuncSetAttribute(gemm_kernel,
                         cudaFuncAttributeMaxDynamicSharedMemorySize, GEMM_SMEM_B);
    dim3 gG(NN / 128, BB * SS / 128);
    gemm_kernel<<<gG, 256, GEMM_SMEM_B>>>(c_b, v_b);

    cudaFuncSetAttribute(attn_scores_kernel,
                         cudaFuncAttributeMaxDynamicSharedMemorySize, ATTN_S_SMEM);
    dim3 gBs(SS / 128, HH, BB);
    attn_scores_kernel<<<gBs, 256, ATTN_S_SMEM>>>(mask, out);

    cudaFuncSetAttribute(attn_pv_kernel,
                         cudaFuncAttributeMaxDynamicSharedMemorySize, ATTN_PV_SMEM);
    dim3 gBp(SS / 64, HH, BB);
    attn_pv_kernel<<<gBp, 256, ATTN_PV_SMEM>>>(m_feats, out);
}

// round 12
// speedup vs baseline: 1.0529x; 1.0529x over previous
#include <cuda_runtime.h>
#include <cuda_bf16.h>
#include <cstdint>

#define BB 8
#define SS 1024
#define DD 1024
#define HH 8
#define DH 128
#define NN 3072
#define SCALE 0.08838834764831845f   // 1/sqrt(128)

// ---------------------------------------------------------------------------
// Device scratch
// ---------------------------------------------------------------------------
__device__ __nv_bfloat16 g_kh[BB*HH*SS*DH];   // K hi  [bh][s][d]
__device__ __nv_bfloat16 g_kl[BB*HH*SS*DH];   // K lo
__device__ __nv_bfloat16 g_qh[BB*HH*SS*DH];   // Q hi  [bh][s][d]
__device__ __nv_bfloat16 g_ql[BB*HH*SS*DH];   // Q lo
__device__ __nv_bfloat16 g_vth[BB*HH*DH*SS];  // V^T hi [bh][d][s]
__device__ __nv_bfloat16 g_Ah[BB*SS*DD];
__device__ __nv_bfloat16 g_Al[BB*SS*DD];
__device__ __nv_bfloat16 g_Wh[NN*DD];
__device__ __nv_bfloat16 g_Wl[NN*DD];

// ---------------------------------------------------------------------------
// Split conversion
// ---------------------------------------------------------------------------
__device__ __forceinline__ void split4(float4 v, __nv_bfloat162* hi2, __nv_bfloat162* lo2) {
    __nv_bfloat16 hx = __float2bfloat16_rn(v.x);
    __nv_bfloat16 hy = __float2bfloat16_rn(v.y);
    __nv_bfloat16 hz = __float2bfloat16_rn(v.z);
    __nv_bfloat16 hw = __float2bfloat16_rn(v.w);
    hi2[0] = __nv_bfloat162(hx, hy);
    hi2[1] = __nv_bfloat162(hz, hw);
    lo2[0] = __nv_bfloat162(__float2bfloat16_rn(v.x - __bfloat162float(hx)),
                            __float2bfloat16_rn(v.y - __bfloat162float(hy)));
    lo2[1] = __nv_bfloat162(__float2bfloat16_rn(v.z - __bfloat162float(hz)),
                            __float2bfloat16_rn(v.w - __bfloat162float(hw)));
}

__global__ __launch_bounds__(256) void convA_kernel(const float* __restrict__ A) {
    int i4 = blockIdx.x * 256 + threadIdx.x;
    if (i4 >= BB*SS*DD/4) return;
    float4 v = ((const float4*)A)[i4];
    __nv_bfloat162 h[2], l[2];
    split4(v, h, l);
    ((__nv_bfloat162*)g_Ah)[i4*2]   = h[0];
    ((__nv_bfloat162*)g_Ah)[i4*2+1] = h[1];
    ((__nv_bfloat162*)g_Al)[i4*2]   = l[0];
    ((__nv_bfloat162*)g_Al)[i4*2+1] = l[1];
}

__global__ __launch_bounds__(256) void convW_kernel(const float* __restrict__ c_w,
                                                    const float* __restrict__ v_w) {
    int i4 = blockIdx.x * 256 + threadIdx.x;
    if (i4 >= NN*DD/4) return;
    int e = i4 * 4;
    int n = e >> 10, k = e & 1023;
    const float* src = (n < DD) ? (v_w + (size_t)n * DD + k)
                                : (c_w + (size_t)(n - DD) * DD + k);
    float4 v = *(const float4*)src;
    __nv_bfloat162 h[2], l[2];
    split4(v, h, l);
    ((__nv_bfloat162*)g_Wh)[i4*2]   = h[0];
    ((__nv_bfloat162*)g_Wh)[i4*2+1] = h[1];
    ((__nv_bfloat162*)g_Wl)[i4*2]   = l[0];
    ((__nv_bfloat162*)g_Wl)[i4*2+1] = l[1];
}

// ---------------------------------------------------------------------------
// helpers
// ---------------------------------------------------------------------------
__device__ __forceinline__ uint32_t smem_u32(const void* p) {
    uint32_t a;
    asm("{ .reg .u64 t; cvta.to.shared.u64 t, %1; cvt.u32.u64 %0, t; }" : "=r"(a) : "l"(p));
    return a;
}
__device__ __forceinline__ void ldsm_x4(uint32_t* r, uint32_t addr) {
    asm volatile("ldmatrix.sync.aligned.m8n8.x4.shared.b16 {%0,%1,%2,%3}, [%4];"
                 : "=r"(r[0]), "=r"(r[1]), "=r"(r[2]), "=r"(r[3]) : "r"(addr));
}
__device__ __forceinline__ void mma_bf16(float* c, const uint32_t* a, uint32_t b0, uint32_t b1) {
    asm volatile(
        "mma.sync.aligned.m16n8k16.row.col.f32.bf16.bf16.f32 "
        "{%0,%1,%2,%3}, {%4,%5,%6,%7}, {%8,%9}, {%0,%1,%2,%3};"
        : "+f"(c[0]), "+f"(c[1]), "+f"(c[2]), "+f"(c[3])
        : "r"(a[0]), "r"(a[1]), "r"(a[2]), "r"(a[3]), "r"(b0), "r"(b1));
}
__device__ __forceinline__ void cpa16ca(uint32_t dst, const void* src) {
    asm volatile("cp.async.ca.shared.global [%0], [%1], 16;" :: "r"(dst), "l"(src));
}
__device__ __forceinline__ void cpa16cg(uint32_t dst, const void* src) {
    asm volatile("cp.async.cg.shared.global [%0], [%1], 16;" :: "r"(dst), "l"(src));
}
#define CP_COMMIT() asm volatile("cp.async.commit_group;")
#define CP_WAIT(n)  asm volatile("cp.async.wait_group %0;" :: "n"(n))

__device__ __forceinline__ void store_hilo(__nv_bfloat16* bh_, __nv_bfloat16* bl_,
                                           size_t off, float x0, float x1) {
    __nv_bfloat16 h0 = __float2bfloat16_rn(x0), h1 = __float2bfloat16_rn(x1);
    *(__nv_bfloat162*)(bh_ + off) = __nv_bfloat162(h0, h1);
    *(__nv_bfloat162*)(bl_ + off) =
        __nv_bfloat162(__float2bfloat16_rn(x0 - __bfloat162float(h0)),
                       __float2bfloat16_rn(x1 - __bfloat162float(h1)));
}

// ---------------------------------------------------------------------------
// Projection GEMM (split-bf16 HMMA): K/Q 3 passes, V 1 pass. occ 2.
// ---------------------------------------------------------------------------
#define KC 32
#define ROWP 40
#define BUF_E (128*ROWP)
#define OFF_AH 0
#define OFF_AL (2*BUF_E)
#define OFF_BH (4*BUF_E)
#define OFF_BL (6*BUF_E)
#define GEMM_SMEM_B (8*BUF_E*2 + 512)

__device__ __forceinline__ void issue_op(uint32_t sdst, const __nv_bfloat16* g,
                                         int tid, int k0) {
#pragma unroll
    for (int j = 0; j < 2; j++) {
        int u = tid + j * 256;
        int row = u >> 2, seg = u & 3;
        cpa16ca(sdst + (uint32_t)(row * ROWP + seg * 8) * 2,
                g + (size_t)row * DD + k0 + seg * 8);
    }
}

__global__ __launch_bounds__(256, 2) void gemm_kernel(const float* __restrict__ c_b,
                                                      const float* __restrict__ v_b) {
    extern __shared__ __nv_bfloat16 sm[];
    float* sBias = (float*)(sm + 8 * BUF_E);
    const uint32_t sbase = smem_u32(sm);

    const int tid  = threadIdx.x;
    const int lane = tid & 31;
    const int wid  = tid >> 5;
    const int wm   = wid >> 1;
    const int wn   = wid & 1;
    const int n0   = blockIdx.x * 128;
    const int m0   = blockIdx.y * 128;
    const int kind = n0 >> 10;
    const bool vpath = (kind == 2);

    const __nv_bfloat16* Ah = g_Ah + (size_t)m0 * DD;
    const __nv_bfloat16* Al = g_Al + (size_t)m0 * DD;
    const __nv_bfloat16* Bh = g_Wh + (size_t)n0 * DD;
    const __nv_bfloat16* Bl = g_Wl + (size_t)n0 * DD;

    const float* bp = (n0 < DD) ? (v_b + n0) : (c_b + (n0 - DD));
    if (tid < 128) sBias[tid] = bp[tid];

    float acc[2][8][4];
#pragma unroll
    for (int i = 0; i < 2; i++)
#pragma unroll
        for (int j = 0; j < 8; j++)
#pragma unroll
            for (int c = 0; c < 4; c++) acc[i][j][c] = 0.f;

    const int lrow_a = wm * 32 + (lane & 15);
    const int lrow_b0 = wn * 64 + (lane & 15);
    const int lk = ((lane >> 4) & 1) * 8;

    {
        issue_op(sbase + OFF_AH * 2, Ah, tid, 0);
        issue_op(sbase + OFF_BH * 2, Bh, tid, 0);
        if (!vpath) {
            issue_op(sbase + OFF_AL * 2, Al, tid, 0);
            issue_op(sbase + OFF_BL * 2, Bl, tid, 0);
        }
        CP_COMMIT();
    }

#pragma unroll 1
    for (int c = 0; c < DD / KC; c++) {
        const int cur = c & 1;
        if (c + 1 < DD / KC) {
            uint32_t bu = sbase + (uint32_t)((cur ^ 1) * BUF_E) * 2;
            int k0 = (c + 1) * KC;
            issue_op(bu + OFF_AH * 2, Ah, tid, k0);
            issue_op(bu + OFF_BH * 2, Bh, tid, k0);
            if (!vpath) {
                issue_op(bu + OFF_AL * 2, Al, tid, k0);
                issue_op(bu + OFF_BL * 2, Bl, tid, k0);
            }
            CP_COMMIT();
            CP_WAIT(1);
        } else {
            CP_WAIT(0);
        }
        __syncthreads();

        const __nv_bfloat16* base = sm + cur * BUF_E;
#pragma unroll
        for (int kk = 0; kk < 2; kk++) {
            const int ke = kk * 16 + lk;
            uint32_t ah[2][4], al[2][4], bh[4][4], bl[4][4];
#pragma unroll
            for (int mi = 0; mi < 2; mi++) {
                uint32_t ad = smem_u32(base + OFF_AH + (lrow_a + mi * 16) * ROWP + ke);
                ldsm_x4(ah[mi], ad);
                if (!vpath) ldsm_x4(al[mi], ad + (OFF_AL - OFF_AH) * 2);
            }
#pragma unroll
            for (int nb = 0; nb < 4; nb++) {
                uint32_t bd = smem_u32(base + OFF_BH + (lrow_b0 + nb * 16) * ROWP + ke);
                ldsm_x4(bh[nb], bd);
                if (!vpath) ldsm_x4(bl[nb], bd + (OFF_BL - OFF_BH) * 2);
            }
            if (vpath) {
#pragma unroll
                for (int mi = 0; mi < 2; mi++)
#pragma unroll
                    for (int nb = 0; nb < 4; nb++) {
                        mma_bf16(acc[mi][nb*2+0], ah[mi], bh[nb][0], bh[nb][2]);
                        mma_bf16(acc[mi][nb*2+1], ah[mi], bh[nb][1], bh[nb][3]);
                    }
            } else {
#pragma unroll
                for (int mi = 0; mi < 2; mi++)
#pragma unroll
                    for (int nb = 0; nb < 4; nb++) {
                        mma_bf16(acc[mi][nb*2+0], ah[mi], bh[nb][0], bh[nb][2]);
                        mma_bf16(acc[mi][nb*2+1], ah[mi], bh[nb][1], bh[nb][3]);
                        mma_bf16(acc[mi][nb*2+0], ah[mi], bl[nb][0], bl[nb][2]);
                        mma_bf16(acc[mi][nb*2+1], ah[mi], bl[nb][1], bl[nb][3]);
                        mma_bf16(acc[mi][nb*2+0], al[mi], bh[nb][0], bh[nb][2]);
                        mma_bf16(acc[mi][nb*2+1], al[mi], bh[nb][1], bh[nb][3]);
                    }
            }
        }
        __syncthreads();
    }

    const int h = (n0 >> 7) & 7;
    const int b_ = m0 >> 10;
    const int g = lane >> 2;
    const int tc = (lane & 3) * 2;
    const size_t bh_off = (size_t)(b_ * HH + h);

#pragma unroll
    for (int mi = 0; mi < 2; mi++) {
#pragma unroll
        for (int nj = 0; nj < 8; nj++) {
            const float* a4 = acc[mi][nj];
            int d = wn * 64 + nj * 8 + tc;
            float bx = sBias[d], by = sBias[d + 1];
            int s0 = (m0 + wm * 32 + mi * 16 + g) & 1023;
            float x0 = a4[0] + bx, x1 = a4[1] + by;
            float x2 = a4[2] + bx, x3 = a4[3] + by;
            if (kind == 2) {
                __nv_bfloat16* dst = g_vth + bh_off * DH * SS;
                dst[(size_t)d * SS + s0]           = __float2bfloat16_rn(x0);
                dst[(size_t)(d + 1) * SS + s0]     = __float2bfloat16_rn(x1);
                dst[(size_t)d * SS + s0 + 8]       = __float2bfloat16_rn(x2);
                dst[(size_t)(d + 1) * SS + s0 + 8] = __float2bfloat16_rn(x3);
            } else {
                __nv_bfloat16* dh_ = (kind == 0) ? g_kh : g_qh;
                __nv_bfloat16* dl_ = (kind == 0) ? g_kl : g_ql;
                size_t base_off = (bh_off * SS + s0) * DH + d;
                store_hilo(dh_, dl_, base_off, x0, x1);
                store_hilo(dh_, dl_, base_off + 8 * DH, x2, x3);
            }
        }
    }
}

// ---------------------------------------------------------------------------
// Monolithic attention v2, TI=64, occ 2.
//   P1: e = exp(score*SCALE) -> out (w region); row sums -> sInv (SMEM only)
//   P3: per 128-j chunk: cp.async e-tile (grpA) + V (grpB); normalize from
//       SMEM while V in flight; w -> global once; bf16 P -> dead K region; MMA
// ---------------------------------------------------------------------------
#define KP 136
#define EPITCH 132                     // floats
#define VPITCH 136
#define PPITCH 136
#define SOFF_K    0                    // P1: Kh(17408)+Kl(17408) | P3: P(17408)
#define SOFF_KL   17408
#define SOFF_U    34816                // P1: Qh(34816)+Ql(34816) | P3: E(33792)+V(34816)
#define SOFF_E    SOFF_U
#define SOFF_V    (SOFF_U + 33792)     // 68608
#define SOFF_MASK 104448
#define SOFF_SUM  108544               // 64 floats
#define SOFF_INV  108800               // 64 floats
#define ATTN_SMEM 109056

__global__ __launch_bounds__(256, 2) void attn_kernel(
    const float* __restrict__ m_feats,
    const int*   __restrict__ mask,
    float* __restrict__ out)
{
    extern __shared__ char smc[];
    int*   sMask = (int*)(smc + SOFF_MASK);
    float* sSum  = (float*)(smc + SOFF_SUM);
    float* sInv  = (float*)(smc + SOFF_INV);
    float*         sE  = (float*)(smc + SOFF_E);
    __nv_bfloat16* sPh = (__nv_bfloat16*)(smc + SOFF_K);
    const uint32_t uKh = smem_u32(smc) + SOFF_K;
    const uint32_t uQh = smem_u32(smc) + SOFF_U;
    const uint32_t uE  = smem_u32(smc) + SOFF_E;
    const uint32_t uV  = smem_u32(smc) + SOFF_V;
    const uint32_t uP  = smem_u32(smc) + SOFF_K;

    const int tid  = threadIdx.x;
    const int lane = tid & 31;
    const int wid  = tid >> 5;
    const int b  = blockIdx.z;
    const int h  = blockIdx.y;
    const int i0 = blockIdx.x * 64;
    const size_t bh = (size_t)(b * HH + h);
    const size_t wbase = (size_t)BB * SS * DD + (bh * SS + i0) * SS;

    const int wm = wid >> 2;        // 0..1 -> rows wm*32
    const int wn = wid & 3;         // 0..3
    const int lr16 = lane & 15;
    const int lkb = (lane >> 4) * 8;
    const int grow = lane >> 2;
    const int gcol = (lane & 3) * 2;

    if (tid < 64) sSum[tid] = 0.f;
    for (int j = tid; j < SS; j += 256) sMask[j] = mask[b * SS + j];
    // K tile fill (64 rows, hi+lo)
#pragma unroll
    for (int it = 0; it < 4; it++) {
        int p = tid + it * 256;
        int row = p >> 4, seg = p & 15;
        size_t go = (bh * SS + i0 + row) * DH + seg * 8;
        uint32_t so = (uint32_t)(row * KP + seg * 8) * 2;
        cpa16cg(uKh + so, g_kh + go);
        cpa16cg(uKh + (SOFF_KL - SOFF_K) + so, g_kl + go);
    }
    CP_COMMIT();
    CP_WAIT(0);
    __syncthreads();

    // ================= Phase 1: e = exp(score) -> global; sums in regs ======
    float psum[2][2] = {{0.f, 0.f}, {0.f, 0.f}};
#pragma unroll 1
    for (int ct = 0; ct < 8; ct++) {
        // Q chunk fill (128 j-rows, hi+lo)
#pragma unroll
        for (int it = 0; it < 8; it++) {
            int p = tid + it * 256;
            int row = p >> 4, seg = p & 15;
            size_t go = (bh * SS + ct * 128 + row) * DH + seg * 8;
            uint32_t so = (uint32_t)(row * KP + seg * 8) * 2;
            cpa16cg(uQh + so, g_qh + go);
            cpa16cg(uQh + 34816 + so, g_ql + go);
        }
        CP_COMMIT();
        CP_WAIT(0);
        __syncthreads();

        float acc[2][4][4];
#pragma unroll
        for (int i = 0; i < 2; i++)
#pragma unroll
            for (int j = 0; j < 4; j++)
#pragma unroll
                for (int cc = 0; cc < 4; cc++) acc[i][j][cc] = 0.f;

#pragma unroll
        for (int ks = 0; ks < 8; ks++) {
            const int ke = ks * 16 + lkb;
            uint32_t kh[2][4], kl[2][4], qh[2][4], ql[2][4];
#pragma unroll
            for (int mi = 0; mi < 2; mi++) {
                uint32_t ad = uKh + (uint32_t)((wm * 32 + mi * 16 + lr16) * KP + ke) * 2;
                ldsm_x4(kh[mi], ad);
                ldsm_x4(kl[mi], ad + (SOFF_KL - SOFF_K));
            }
#pragma unroll
            for (int nb = 0; nb < 2; nb++) {
                uint32_t bd = uQh + (uint32_t)((wn * 32 + nb * 16 + lr16) * KP + ke) * 2;
                ldsm_x4(qh[nb], bd);
                ldsm_x4(ql[nb], bd + 34816);
            }
#pragma unroll
            for (int mi = 0; mi < 2; mi++)
#pragma unroll
                for (int nb = 0; nb < 2; nb++) {
                    mma_bf16(acc[mi][nb*2+0], kh[mi], qh[nb][0], qh[nb][2]);
                    mma_bf16(acc[mi][nb*2+1], kh[mi], qh[nb][1], qh[nb][3]);
                    mma_bf16(acc[mi][nb*2+0], kh[mi], ql[nb][0], ql[nb][2]);
                    mma_bf16(acc[mi][nb*2+1], kh[mi], ql[nb][1], ql[nb][3]);
                    mma_bf16(acc[mi][nb*2+0], kl[mi], qh[nb][0], qh[nb][2]);
                    mma_bf16(acc[mi][nb*2+1], kl[mi], qh[nb][1], qh[nb][3]);
                }
        }

#pragma unroll
        for (int mi = 0; mi < 2; mi++)
#pragma unroll
            for (int nj = 0; nj < 4; nj++) {
                int jg = ct * 128 + wn * 32 + (nj >> 1) * 16 + (nj & 1) * 8 + gcol;
                bool m0 = sMask[jg] != 0, m1 = sMask[jg + 1] != 0;
                int ir = wm * 32 + mi * 16 + grow;
                const float* a4 = acc[mi][nj];
                float2 r0, r1;
                r0.x = m0 ? __expf(a4[0] * SCALE) : 1e-37f;
                r0.y = m1 ? __expf(a4[1] * SCALE) : 1e-37f;
                r1.x = m0 ? __expf(a4[2] * SCALE) : 1e-37f;
                r1.y = m1 ? __expf(a4[3] * SCALE) : 1e-37f;
                psum[mi][0] += r0.x + r0.y;
                psum[mi][1] += r1.x + r1.y;
                *(float2*)&out[wbase + (size_t)ir * SS + jg]       = r0;
                *(float2*)&out[wbase + (size_t)(ir + 8) * SS + jg] = r1;
            }
        __syncthreads();
    }

    // row-sum reduction -> sInv (SMEM only)
#pragma unroll
    for (int mi = 0; mi < 2; mi++)
#pragma unroll
        for (int hf = 0; hf < 2; hf++) {
            psum[mi][hf] += __shfl_xor_sync(~0u, psum[mi][hf], 1);
            psum[mi][hf] += __shfl_xor_sync(~0u, psum[mi][hf], 2);
        }
    if ((lane & 3) == 0) {
#pragma unroll
        for (int mi = 0; mi < 2; mi++) {
            atomicAdd(&sSum[wm * 32 + mi * 16 + grow],     psum[mi][0]);
            atomicAdd(&sSum[wm * 32 + mi * 16 + grow + 8], psum[mi][1]);
        }
    }
    __syncthreads();
    if (tid < 64) sInv[tid] = 1.0f / sSum[tid];
    __threadfence_block();
    __syncthreads();

    // ================= Phase 3: normalize + PV (e prefetched) ===============
    float racc[2][4][4];
#pragma unroll
    for (int i = 0; i < 2; i++)
#pragma unroll
        for (int j = 0; j < 4; j++)
#pragma unroll
            for (int cc = 0; cc < 4; cc++) racc[i][j][cc] = 0.f;

    const int crow = tid >> 2;          // 0..63
    const int cq   = tid & 3;

#pragma unroll 1
    for (int jc = 0; jc < 8; jc++) {
        // group A: e tile (64 rows x 128 fp32)
#pragma unroll
        for (int it = 0; it < 8; it++) {
            int p = tid + it * 256;
            int row = p >> 5, seg = p & 31;
            cpa16cg(uE + (uint32_t)(row * EPITCH + seg * 4) * 4,
                    out + wbase + (size_t)row * SS + jc * 128 + seg * 4);
        }
        CP_COMMIT();
        // group B: V tile (128 d-rows x 128 j bf16)
#pragma unroll
        for (int it = 0; it < 8; it++) {
            int p = tid + it * 256;
            int row = p >> 4, seg = p & 15;
            cpa16cg(uV + (uint32_t)(row * VPITCH + seg * 8) * 2,
                    g_vth + (bh * DH + row) * SS + jc * 128 + seg * 8);
        }
        CP_COMMIT();

        CP_WAIT(1);                 // e ready; V in flight
        __syncthreads();

        // normalize from SMEM: w -> global, bf16 w -> P tile (overlaps V load)
        {
            float inv = sInv[crow];
            const float* erow = sE + crow * EPITCH;
            float* wrow = out + wbase + (size_t)crow * SS + jc * 128;
#pragma unroll
            for (int k = 0; k < 8; k++) {
                int col = cq * 4 + k * 16;
                float4 e4 = *(const float4*)&erow[col];
                float4 w4;
                w4.x = e4.x * inv; w4.y = e4.y * inv;
                w4.z = e4.z * inv; w4.w = e4.w * inv;
                *(float4*)&wrow[col] = w4;
                union { uint2 u; __nv_bfloat162 b2[2]; } pk;
                pk.b2[0] = __nv_bfloat162(__float2bfloat16_rn(w4.x), __float2bfloat16_rn(w4.y));
                pk.b2[1] = __nv_bfloat162(__float2bfloat16_rn(w4.z), __float2bfloat16_rn(w4.w));
                *(uint2*)&sPh[crow * PPITCH + col] = pk.u;
            }
        }
        CP_WAIT(0);                 // V ready
        __syncthreads();

#pragma unroll
        for (int ks = 0; ks < 8; ks++) {
            const int ke = ks * 16 + lkb;
            uint32_t pa[2][4], vh[2][4];
#pragma unroll
            for (int mi = 0; mi < 2; mi++)
                ldsm_x4(pa[mi], uP + (uint32_t)((wm * 32 + mi * 16 + lr16) * PPITCH + ke) * 2);
#pragma unroll
            for (int nb = 0; nb < 2; nb++)
                ldsm_x4(vh[nb], uV + (uint32_t)((wn * 32 + nb * 16 + lr16) * VPITCH + ke) * 2);
#pragma unroll
            for (int mi = 0; mi < 2; mi++)
#pragma unroll
                for (int nb = 0; nb < 2; nb++) {
                    mma_bf16(racc[mi][nb*2+0], pa[mi], vh[nb][0], vh[nb][2]);
                    mma_bf16(racc[mi][nb*2+1], pa[mi], vh[nb][1], vh[nb][3]);
                }
        }
        __syncthreads();
    }

    // epilogue: out = m_feats + R (P normalized)
#pragma unroll
    for (int mi = 0; mi < 2; mi++)
#pragma unroll
        for (int nj = 0; nj < 4; nj++) {
            int d = wn * 32 + (nj >> 1) * 16 + (nj & 1) * 8 + gcol;
            int ir = wm * 32 + mi * 16 + grow;
            const float* a4 = racc[mi][nj];
            size_t o0 = ((size_t)b * SS + i0 + ir) * DD + h * DH + d;
            float2 mf0 = *(const float2*)&m_feats[o0];
            *(float2*)&out[o0] = make_float2(mf0.x + a4[0], mf0.y + a4[1]);
            size_t o1 = o0 + (size_t)8 * DD;
            float2 mf1 = *(const float2*)&m_feats[o1];
            *(float2*)&out[o1] = make_float2(mf1.x + a4[2], mf1.y + a4[3]);
        }
}

// ---------------------------------------------------------------------------
extern "C" void kernel_launch(void* const* d_in, const int* in_sizes, int n_in,
                              void* d_out, int out_size)
{
    const float* m_feats = (const float*)d_in[0];
    const int*   mask    = (const int*)d_in[1];
    const float* c_w     = (const float*)d_in[2];
    const float* c_b     = (const float*)d_in[3];
    const float* v_w     = (const float*)d_in[4];
    const float* v_b     = (const float*)d_in[5];
    float* out = (float*)d_out;

    convA_kernel<<<BB*SS*DD/4/256, 256>>>(m_feats);
    convW_kernel<<<NN*DD/4/256, 256>>>(c_w, v_w);

    cudaFuncSetAttribute(gemm_kernel,
                         cudaFuncAttributeMaxDynamicSharedMemorySize, GEMM_SMEM_B);
    dim3 gG(NN / 128, BB * SS / 128);
    gemm_kernel<<<gG, 256, GEMM_SMEM_B>>>(c_b, v_b);

    cudaFuncSetAttribute(attn_kernel,
                         cudaFuncAttributeMaxDynamicSharedMemorySize, ATTN_SMEM);
    dim3 gB(SS / 64, HH, BB);
    attn_kernel<<<gB, 256, ATTN_SMEM>>>(m_feats, mask, out);
}